// round 15
// baseline (speedup 1.0000x reference)
#include <cuda_runtime.h>

#define T_STEPS 1000
#define B_TOT   256
#define FIN     39
#define H       100
#define G3      300
#define NCLS    20
#define GSTR    (B_TOT * G3)
#define NPROD   20
#define NREC    128
#define NCTAS   (NREC + NPROD)

typedef unsigned long long u64;

// 307 MB scratch for precomputed input gates gi[t][b][g] (includes b_ih)
__device__ float g_gi[(size_t)T_STEPS * B_TOT * G3];
// producer progress: g_flagi[p] = count of finished t's with t%NPROD==p
__device__ int g_flagi[NPROD];
// all-CTA completion counter (for end-of-launch flag reset)
__device__ int g_done;

__device__ __forceinline__ u64 pk(float x, float y) {
    u64 r; asm("mov.b64 %0,{%1,%2};" : "=l"(r) : "f"(x), "f"(y)); return r;
}
__device__ __forceinline__ void fma2(u64 &d, u64 a, u64 b) {
    asm("fma.rn.f32x2 %0,%1,%2,%0;" : "+l"(d) : "l"(a), "l"(b));
}
__device__ __forceinline__ u64 add2(u64 a, u64 b) {
    u64 r; asm("add.rn.f32x2 %0,%1,%2;" : "=l"(r) : "l"(a), "l"(b)); return r;
}
__device__ __forceinline__ float hsum2(u64 a) {
    float x, y; asm("mov.b64 {%0,%1},%2;" : "=f"(x), "=f"(y) : "l"(a)); return x + y;
}
__device__ __forceinline__ void lds_v2u64(u64 &a, u64 &b, unsigned addr) {
    asm volatile("ld.shared.v2.u64 {%0,%1},[%2];" : "=l"(a), "=l"(b) : "r"(addr));
}
__device__ __forceinline__ float sigf(float x) {
    return __fdividef(1.0f, 1.0f + __expf(-x));
}
__device__ __forceinline__ float tanh_acc(float x) {
    return 2.0f * sigf(2.0f * x) - 1.0f;
}

// wait until ALL gi(t') for t' <= tneed (clamped) are published.
// Batched: all 20 flag loads issued before any branch (MLP=20, one latency).
__device__ __forceinline__ void wait_gi(int tneed) {
    if (tneed > T_STEPS - 1) tneed = T_STEPS - 1;
    for (;;) {
        int cnt[NPROD];
        #pragma unroll
        for (int p = 0; p < NPROD; p++)
            cnt[p] = ((volatile int*)g_flagi)[p];
        bool ok = true;
        #pragma unroll
        for (int p = 0; p < NPROD; p++) {
            int req = (tneed >= p) ? ((tneed - p) / NPROD + 1) : 0;
            ok &= (cnt[p] >= req);
        }
        if (ok) break;
        __nanosleep(256);
    }
    __threadfence();   // acquire: order subsequent gi reads after flags
}

#define CH   28          // rec chunk floats (112B, 16B-aligned, conflict-free)
#define HP   112         // padded h floats per batch
#define PPH  64          // producer pairs per phase
#define PBUF (PPH * 40 * 4)   // bytes per producer x buffer (10240)

__global__ void __launch_bounds__(400, 1) gru_fused_kernel(
    const float* __restrict__ mfcc0, const float* __restrict__ mfcc1,
    const float* __restrict__ mfcc2, const float* __restrict__ len0,
    const float* __restrict__ W_ih, const float* __restrict__ W_hh,
    const float* __restrict__ b_ih, const float* __restrict__ b_hh,
    const float* __restrict__ W_out, const float* __restrict__ b_out,
    float* __restrict__ out)
{
    __shared__ __align__(16) float xt[2][PPH][40];   // producer x (20.5KB)
    __shared__ __align__(16) float h_sh[2][2][HP];   // rec h state
    __shared__ float feat_sh[2][2 * H];

    const int tid = threadIdx.x;

    // =====================================================================
    // PRODUCER CTAs: blockIdx 128..147, residue p = blockIdx-128.
    // gi[t][b][g] = b_ih[g] + sum_k x[t][b][k] * W_ih[g][k]
    // Per t: 4 phases of 64 pairs. Next phase's x LDG'd into regs BEFORE the
    // compute burst, STS'd after -> LDG latency hidden. 1 barrier per phase.
    // =====================================================================
    if (blockIdx.x >= NREC) {
        const int p = blockIdx.x - NREC;
        const int g = (tid < G3) ? tid : (G3 - 1);
        const bool act = (tid < G3);

        u64 wih[20];
        {
            const float* wsrc = W_ih + g * FIN;
            #pragma unroll
            for (int j = 0; j < 19; j++) wih[j] = pk(wsrc[2 * j], wsrc[2 * j + 1]);
            wih[19] = pk(wsrc[38], 0.0f);
        }
        const float bias = b_ih[g];

        // fill-slot assignment (threads < 320): 8 slots of the 2560-slot tile
        const bool fl = (tid < 320);
        const float* fb[8];
        int fpr[8], soff[8];
        bool fok[8];
        #pragma unroll
        for (int s = 0; s < 8; s++) {
            int idx = (fl ? tid : 0) + s * 320;
            int pr = idx / 40, k = idx - pr * 40;
            fpr[s] = pr;
            soff[s] = pr * 160 + k * 4;
            fok[s] = fl && (k < 39);
            const float* src = (k < 13) ? mfcc0 : (k < 26) ? mfcc1 : mfcc2;
            int f = (k < 13) ? k : (k < 26) ? (k - 13) : (k - 26);
            fb[s] = src + f;
        }

        const unsigned xB = (unsigned)__cvta_generic_to_shared(&xt[0][0][0]);

        // prologue: fill buf0 with (t=p, phase 0)
        {
            int pbase = p * B_TOT;
            #pragma unroll
            for (int s = 0; s < 8; s++)
                ((float*)xt)[soff[s] / 4] =
                    fok[s] ? __ldg(fb[s] + (size_t)(pbase + fpr[s]) * 13) : 0.0f;
        }
        __syncthreads();

        for (int t = p; t < T_STEPS; t += NPROD) {
            for (int ph = 0; ph < 4; ph++) {
                const int pbase = t * B_TOT + ph * PPH;
                const int buf = ph & 1;

                // next phase coordinates (or next t's phase 0)
                int npbase = -1;
                if (ph < 3)                    npbase = pbase + PPH;
                else if (t + NPROD < T_STEPS)  npbase = (t + NPROD) * B_TOT;

                // LDG next phase x into regs (latency hidden by compute below)
                float v[8];
                if (npbase >= 0) {
                    #pragma unroll
                    for (int s = 0; s < 8; s++)
                        v[s] = fok[s] ? __ldg(fb[s] + (size_t)(npbase + fpr[s]) * 13)
                                      : 0.0f;
                }

                // compute current phase: 64 pairs
                const unsigned xA = xB + buf * PBUF;
                #pragma unroll 2
                for (int pair = 0; pair < PPH; pair += 2) {
                    u64 a0 = 0, a1 = 0, c0 = 0, c1 = 0;
                    unsigned ad = xA + pair * 160;
                    #pragma unroll
                    for (int j = 0; j < 10; j++) {
                        u64 q, r, q2, r2;
                        lds_v2u64(q,  r,  ad + j * 16);
                        lds_v2u64(q2, r2, ad + 160 + j * 16);
                        fma2(a0, wih[2 * j],     q);
                        fma2(a1, wih[2 * j + 1], r);
                        fma2(c0, wih[2 * j],     q2);
                        fma2(c1, wih[2 * j + 1], r2);
                    }
                    if (act) {
                        g_gi[(size_t)(pbase + pair) * G3 + g]     = hsum2(add2(a0, a1)) + bias;
                        g_gi[(size_t)(pbase + pair + 1) * G3 + g] = hsum2(add2(c0, c1)) + bias;
                    }
                }

                // publish next-phase x into the other buffer
                if (npbase >= 0) {
                    float* dst = (float*)xt + (buf ^ 1) * (PBUF / 4);
                    #pragma unroll
                    for (int s = 0; s < 8; s++)
                        if (fl) dst[soff[s] / 4] = v[s];
                }
                __syncthreads();
            }
            // t complete: release-fence + flag
            if (tid == 0) {
                __threadfence();
                atomicAdd(&g_flagi[p], 1);
            }
        }

        __syncthreads();
        if (tid == 0) {
            int d = atomicAdd(&g_done, 1);
            if (d == NCTAS - 1) {
                #pragma unroll
                for (int i = 0; i < NPROD; i++) g_flagi[i] = 0;
                __threadfence();
                g_done = 0;
            }
        }
        return;
    }

    // =====================================================================
    // RECURRENT CTAs: blockIdx 0..127 — R3 kernel (measured 931us) +
    // batched frontier waits. thread = (h = tid>>2, chunk c = tid&3).
    // =====================================================================
    const int h   = tid >> 2;          // 0..99
    const int c   = tid & 3;           // K-chunk, and batch selector for c<2
    const int b0  = blockIdx.x * 2;
    const unsigned smask = (tid < 384) ? 0xFFFFFFFFu : 0x0000FFFFu;

    for (int i = tid; i < 2 * 2 * HP; i += 400) ((float*)h_sh)[i] = 0.0f;

    const int k0   = c * CH;
    const int kcnt = (k0 + CH <= H) ? CH : (H - k0);   // 28 or 16
    u64 w[3][CH / 2];
    #pragma unroll
    for (int i = 0; i < 3; i++) {
        const float* wr = W_hh + (h + i * H) * H + k0;
        #pragma unroll
        for (int j = 0; j < CH / 2; j++) {
            float x0 = (2 * j     < kcnt) ? wr[2 * j]     : 0.0f;
            float x1 = (2 * j + 1 < kcnt) ? wr[2 * j + 1] : 0.0f;
            w[i][j] = pk(x0, x1);
        }
    }

    const bool fin = (c < 2);
    float bh0 = 0.0f, bh1 = 0.0f, bh2 = 0.0f;
    const float* gp = g_gi;
    if (fin) {
        bh0 = b_hh[h]; bh1 = b_hh[h + H]; bh2 = b_hh[h + 2 * H];
        gp = g_gi + (size_t)(b0 + c) * G3 + h;
    }
    float hprev = 0.0f, hs = 0.0f, hm = -1e30f;

    // wait for gi(0..16) before first reads
    if (tid == 0) wait_gi(16);
    __syncthreads();

    float gv0 = 0.0f, gv1 = 0.0f, gv2 = 0.0f;
    if (fin) { gv0 = __ldcg(gp); gv1 = __ldcg(gp + H); gv2 = __ldcg(gp + 2 * H); }

    const unsigned hB = (unsigned)__cvta_generic_to_shared(&h_sh[0][0][0]) + c * (CH * 4);
    int bp = 0;

    for (int t = 0; t < T_STEPS; t++) {
        float gn0 = 0.0f, gn1 = 0.0f, gn2 = 0.0f;
        if (fin && t + 1 < T_STEPS) {
            const float* gq = gp + (size_t)(t + 1) * GSTR;
            gn0 = __ldcg(gq); gn1 = __ldcg(gq + H); gn2 = __ldcg(gq + 2 * H);
        }

        u64 a00 = 0, a01 = 0, a10 = 0, a11 = 0, a20 = 0, a21 = 0;   // batch 0
        u64 d00 = 0, d01 = 0, d10 = 0, d11 = 0, d20 = 0, d21 = 0;   // batch 1
        {
            const unsigned ad = hB + bp * (2 * HP * 4);
            #pragma unroll
            for (int j = 0; j < CH / 4; j++) {           // 7 iters, 16B each
                u64 q0, q1, r0, r1;
                lds_v2u64(q0, q1, ad + j * 16);                  // batch 0
                lds_v2u64(r0, r1, ad + HP * 4 + j * 16);         // batch 1
                fma2(a00, w[0][2 * j], q0); fma2(a01, w[0][2 * j + 1], q1);
                fma2(a10, w[1][2 * j], q0); fma2(a11, w[1][2 * j + 1], q1);
                fma2(a20, w[2][2 * j], q0); fma2(a21, w[2][2 * j + 1], q1);
                fma2(d00, w[0][2 * j], r0); fma2(d01, w[0][2 * j + 1], r1);
                fma2(d10, w[1][2 * j], r0); fma2(d11, w[1][2 * j + 1], r1);
                fma2(d20, w[2][2 * j], r0); fma2(d21, w[2][2 * j + 1], r1);
            }
        }
        float s0b0 = hsum2(add2(a00, a01));
        float s1b0 = hsum2(add2(a10, a11));
        float s2b0 = hsum2(add2(a20, a21));
        float s0b1 = hsum2(add2(d00, d01));
        float s1b1 = hsum2(add2(d10, d11));
        float s2b1 = hsum2(add2(d20, d21));

        s0b0 += __shfl_xor_sync(smask, s0b0, 1); s0b0 += __shfl_xor_sync(smask, s0b0, 2);
        s1b0 += __shfl_xor_sync(smask, s1b0, 1); s1b0 += __shfl_xor_sync(smask, s1b0, 2);
        s2b0 += __shfl_xor_sync(smask, s2b0, 1); s2b0 += __shfl_xor_sync(smask, s2b0, 2);
        s0b1 += __shfl_xor_sync(smask, s0b1, 1); s0b1 += __shfl_xor_sync(smask, s0b1, 2);
        s1b1 += __shfl_xor_sync(smask, s1b1, 1); s1b1 += __shfl_xor_sync(smask, s1b1, 2);
        s2b1 += __shfl_xor_sync(smask, s2b1, 1); s2b1 += __shfl_xor_sync(smask, s2b1, 2);

        if (fin) {
            float hr = (c == 0) ? s0b0 : s0b1;
            float hz = (c == 0) ? s1b0 : s1b1;
            float hn = (c == 0) ? s2b0 : s2b1;
            float r = sigf(gv0 + hr + bh0);
            float z = sigf(gv1 + hz + bh1);
            float n = tanh_acc(gv2 + r * (hn + bh2));
            float hnew = n + z * (hprev - n);
            hprev = hnew;
            hs += hnew;
            hm = fmaxf(hm, hnew);
            h_sh[1 - bp][c][h] = hnew;
        }
        gv0 = gn0; gv1 = gn1; gv2 = gn2;

        // frontier check every 16 steps: cover prefetches through gi(t+17)
        if ((t & 15) == 15 && tid == 0) wait_gi(t + 17);
        __syncthreads();
        bp ^= 1;
    }

    if (fin) {
        float inv = 1.0f / len0[b0 + c];
        feat_sh[c][h]     = hs * inv;
        feat_sh[c][H + h] = hm;
    }
    __syncthreads();

    if (tid < 2 * NCLS) {
        int bb = tid / NCLS, cc = tid % NCLS;
        const float* wr = W_out + cc * 2 * H;
        float acc = b_out[cc];
        #pragma unroll 4
        for (int j = 0; j < 2 * H; j++) acc += feat_sh[bb][j] * wr[j];
        out[(b0 + bb) * NCLS + cc] = acc;
    }
    __syncthreads();

    if (tid == 0) {
        int d = atomicAdd(&g_done, 1);
        if (d == NCTAS - 1) {
            #pragma unroll
            for (int i = 0; i < NPROD; i++) g_flagi[i] = 0;
            __threadfence();
            g_done = 0;
        }
    }
}

extern "C" void kernel_launch(void* const* d_in, const int* in_sizes, int n_in,
                              void* d_out, int out_size)
{
    const float* mfcc0 = (const float*)d_in[0];
    const float* mfcc1 = (const float*)d_in[1];
    const float* mfcc2 = (const float*)d_in[2];
    const float* len0  = (const float*)d_in[3];
    const float* W_ih  = (const float*)d_in[4];
    const float* W_hh  = (const float*)d_in[5];
    const float* b_ih  = (const float*)d_in[6];
    const float* b_hh  = (const float*)d_in[7];
    const float* W_out = (const float*)d_in[8];
    const float* b_out = (const float*)d_in[9];
    float* out = (float*)d_out;

    gru_fused_kernel<<<NCTAS, 400>>>(mfcc0, mfcc1, mfcc2, len0,
                                     W_ih, W_hh, b_ih, b_hh,
                                     W_out, b_out, out);
}

// round 16
// speedup vs baseline: 1.2424x; 1.2424x over previous
#include <cuda_runtime.h>

#define T_STEPS 1000
#define B_TOT   256
#define FIN     39
#define H       100
#define G3      300
#define NCLS    20
#define GSTR    (G3 * B_TOT)     // floats per t in gi[t][g][b]
#define HB      (H * B_TOT)
#define NPROD   20
#define NREC    128
#define NCTAS   (NREC + NPROD)

typedef unsigned long long u64;

// 307 MB scratch: gi[t][g][b] = b_ih[g] + sum_k x[t][b][k]*W_ih[g][k]
__device__ float g_gi[(size_t)T_STEPS * G3 * B_TOT];
// producer progress: g_flagi[p] = count of finished t's with t%NPROD==p
__device__ int g_flagi[NPROD];
__device__ int g_done;

__device__ __forceinline__ u64 pk(float x, float y) {
    u64 r; asm("mov.b64 %0,{%1,%2};" : "=l"(r) : "f"(x), "f"(y)); return r;
}
__device__ __forceinline__ void fma2(u64 &d, u64 a, u64 b) {
    asm("fma.rn.f32x2 %0,%1,%2,%0;" : "+l"(d) : "l"(a), "l"(b));
}
__device__ __forceinline__ u64 add2(u64 a, u64 b) {
    u64 r; asm("add.rn.f32x2 %0,%1,%2;" : "=l"(r) : "l"(a), "l"(b)); return r;
}
__device__ __forceinline__ float hsum2(u64 a) {
    float x, y; asm("mov.b64 {%0,%1},%2;" : "=f"(x), "=f"(y) : "l"(a)); return x + y;
}
__device__ __forceinline__ void lds_v2u64(u64 &a, u64 &b, unsigned addr) {
    asm volatile("ld.shared.v2.u64 {%0,%1},[%2];" : "=l"(a), "=l"(b) : "r"(addr));
}
__device__ __forceinline__ float sigf(float x) {
    return __fdividef(1.0f, 1.0f + __expf(-x));
}
__device__ __forceinline__ float tanh_acc(float x) {
    return 2.0f * sigf(2.0f * x) - 1.0f;
}

// wait until ALL gi(t') for t' <= tneed (clamped) are published.
// Batched: all 20 flag loads issued before any branch.
__device__ __forceinline__ void wait_gi(int tneed) {
    if (tneed > T_STEPS - 1) tneed = T_STEPS - 1;
    for (;;) {
        int cnt[NPROD];
        #pragma unroll
        for (int p = 0; p < NPROD; p++)
            cnt[p] = ((volatile int*)g_flagi)[p];
        bool ok = true;
        #pragma unroll
        for (int p = 0; p < NPROD; p++) {
            int req = (tneed >= p) ? ((tneed - p) / NPROD + 1) : 0;
            ok &= (cnt[p] >= req);
        }
        if (ok) break;
        __nanosleep(256);
    }
    __threadfence();   // acquire
}

#define CH  28           // rec chunk floats
#define HP  112          // padded h floats per batch

// union-aliased shared buffer: producer uses 48000B W_ih table; rec uses ~5.2KB
struct RecShm {
    float h[2][2][HP];
    float feat[2][2 * H];
};

__global__ void __launch_bounds__(400, 1) gru_fused_kernel(
    const float* __restrict__ mfcc0, const float* __restrict__ mfcc1,
    const float* __restrict__ mfcc2, const float* __restrict__ len0,
    const float* __restrict__ W_ih, const float* __restrict__ W_hh,
    const float* __restrict__ b_ih, const float* __restrict__ b_hh,
    const float* __restrict__ W_out, const float* __restrict__ b_out,
    float* __restrict__ out)
{
    __shared__ __align__(16) unsigned char smem_raw[G3 * 40 * 4];   // 48000 B

    const int tid = threadIdx.x;

    // =====================================================================
    // PRODUCER CTAs: blockIdx 128..147, residue p.
    // Pair-stationary: thread holds x for 2 consecutive pairs in regs
    // (x[39]=1.0; bias folded as w_sh[g][39]=b_ih[g]); loops 300 gates
    // reading W rows from smem broadcast (10 LDS feed 40 fma2 -> 1:4).
    // gi layout [t][g][b] -> STG.64 coalesced. 16 rounds x 800 pairs,
    // one barrier + flag per round.
    // =====================================================================
    if (blockIdx.x >= NREC) {
        const int p = blockIdx.x - NREC;
        float* w_sh = (float*)smem_raw;          // [G3][40], [g][39]=bias

        for (int i = tid; i < G3 * 40; i += 400) {
            int g = i / 40, k = i - g * 40;
            w_sh[i] = (k < FIN) ? W_ih[g * FIN + k] : b_ih[g];
        }
        __syncthreads();

        const unsigned wB = (unsigned)__cvta_generic_to_shared(w_sh);

        for (int r = 0; r < 16; r++) {
            const int idx = r * 800 + 2 * tid;   // flattened (ti, b) pair index
            const int ti  = idx >> 8;            // /256
            const int b   = idx & 255;
            const int t   = p + NPROD * ti;

            // load x for 2 pairs into regs (39 feats + 1.0 pad each)
            u64 xa[20], xb[20];
            {
                const size_t rowA = (size_t)t * B_TOT + b;
                const float* a0 = mfcc0 + rowA * 13;
                const float* a1 = mfcc1 + rowA * 13;
                const float* a2 = mfcc2 + rowA * 13;
                float f[40];
                #pragma unroll
                for (int j = 0; j < 13; j++) {
                    f[j] = a0[j]; f[13 + j] = a1[j]; f[26 + j] = a2[j];
                }
                f[39] = 1.0f;
                #pragma unroll
                for (int i = 0; i < 20; i++) xa[i] = pk(f[2 * i], f[2 * i + 1]);
                #pragma unroll
                for (int j = 0; j < 13; j++) {
                    f[j] = a0[13 + j]; f[13 + j] = a1[13 + j]; f[26 + j] = a2[13 + j];
                }
                f[39] = 1.0f;
                #pragma unroll
                for (int i = 0; i < 20; i++) xb[i] = pk(f[2 * i], f[2 * i + 1]);
            }

            float* gout = g_gi + (size_t)t * GSTR + b;   // + g*B_TOT per gate

            #pragma unroll 1
            for (int g = 0; g < G3; g++) {
                const unsigned wa = wB + (unsigned)(g * 160);
                u64 pa0 = 0, pa1 = 0, pb0 = 0, pb1 = 0;
                #pragma unroll
                for (int j = 0; j < 10; j++) {
                    u64 w0, w1;
                    lds_v2u64(w0, w1, wa + j * 16);
                    fma2(pa0, w0, xa[2 * j]); fma2(pa1, w1, xa[2 * j + 1]);
                    fma2(pb0, w0, xb[2 * j]); fma2(pb1, w1, xb[2 * j + 1]);
                }
                float va = hsum2(add2(pa0, pa1));
                float vb = hsum2(add2(pb0, pb1));
                *(u64*)(gout + (size_t)g * B_TOT) = pk(va, vb);
            }

            __syncthreads();   // round complete across CTA
            if (tid == 0) {
                __threadfence();                       // release gi stores
                atomicExch(&g_flagi[p], (800 * (r + 1)) / 256);
            }
        }

        __syncthreads();
        if (tid == 0) {
            int d = atomicAdd(&g_done, 1);
            if (d == NCTAS - 1) {
                #pragma unroll
                for (int i = 0; i < NPROD; i++) g_flagi[i] = 0;
                __threadfence();
                g_done = 0;
            }
        }
        return;
    }

    // =====================================================================
    // RECURRENT CTAs: blockIdx 0..127 — R3 kernel (measured 931us) with
    // gi[t][g][b] addressing + batched frontier waits.
    // =====================================================================
    RecShm* rs = (RecShm*)smem_raw;
    const int h   = tid >> 2;          // 0..99
    const int c   = tid & 3;           // K-chunk; batch selector for c<2
    const int b0  = blockIdx.x * 2;
    const unsigned smask = (tid < 384) ? 0xFFFFFFFFu : 0x0000FFFFu;

    for (int i = tid; i < 2 * 2 * HP; i += 400) ((float*)rs->h)[i] = 0.0f;

    const int k0   = c * CH;
    const int kcnt = (k0 + CH <= H) ? CH : (H - k0);   // 28 or 16
    u64 w[3][CH / 2];
    #pragma unroll
    for (int i = 0; i < 3; i++) {
        const float* wr = W_hh + (h + i * H) * H + k0;
        #pragma unroll
        for (int j = 0; j < CH / 2; j++) {
            float x0 = (2 * j     < kcnt) ? wr[2 * j]     : 0.0f;
            float x1 = (2 * j + 1 < kcnt) ? wr[2 * j + 1] : 0.0f;
            w[i][j] = pk(x0, x1);
        }
    }

    const bool fin = (c < 2);
    float bh0 = 0.0f, bh1 = 0.0f, bh2 = 0.0f;
    const float* gp = g_gi;
    if (fin) {
        bh0 = b_hh[h]; bh1 = b_hh[h + H]; bh2 = b_hh[h + 2 * H];
        gp = g_gi + (size_t)h * B_TOT + (b0 + c);      // [t=0][h][b]
    }
    float hprev = 0.0f, hs = 0.0f, hm = -1e30f;

    if (tid == 0) wait_gi(16);
    __syncthreads();

    float gv0 = 0.0f, gv1 = 0.0f, gv2 = 0.0f;
    if (fin) { gv0 = __ldcg(gp); gv1 = __ldcg(gp + HB); gv2 = __ldcg(gp + 2 * HB); }

    const unsigned hBq = (unsigned)__cvta_generic_to_shared(&rs->h[0][0][0]) + c * (CH * 4);
    int bp = 0;

    for (int t = 0; t < T_STEPS; t++) {
        float gn0 = 0.0f, gn1 = 0.0f, gn2 = 0.0f;
        if (fin && t + 1 < T_STEPS) {
            const float* gq = gp + (size_t)(t + 1) * GSTR;
            gn0 = __ldcg(gq); gn1 = __ldcg(gq + HB); gn2 = __ldcg(gq + 2 * HB);
        }

        u64 a00 = 0, a01 = 0, a10 = 0, a11 = 0, a20 = 0, a21 = 0;   // batch 0
        u64 d00 = 0, d01 = 0, d10 = 0, d11 = 0, d20 = 0, d21 = 0;   // batch 1
        {
            const unsigned ad = hBq + bp * (2 * HP * 4);
            #pragma unroll
            for (int j = 0; j < CH / 4; j++) {           // 7 iters, 16B each
                u64 q0, q1, r0, r1;
                lds_v2u64(q0, q1, ad + j * 16);
                lds_v2u64(r0, r1, ad + HP * 4 + j * 16);
                fma2(a00, w[0][2 * j], q0); fma2(a01, w[0][2 * j + 1], q1);
                fma2(a10, w[1][2 * j], q0); fma2(a11, w[1][2 * j + 1], q1);
                fma2(a20, w[2][2 * j], q0); fma2(a21, w[2][2 * j + 1], q1);
                fma2(d00, w[0][2 * j], r0); fma2(d01, w[0][2 * j + 1], r1);
                fma2(d10, w[1][2 * j], r0); fma2(d11, w[1][2 * j + 1], r1);
                fma2(d20, w[2][2 * j], r0); fma2(d21, w[2][2 * j + 1], r1);
            }
        }
        float s0b0 = hsum2(add2(a00, a01));
        float s1b0 = hsum2(add2(a10, a11));
        float s2b0 = hsum2(add2(a20, a21));
        float s0b1 = hsum2(add2(d00, d01));
        float s1b1 = hsum2(add2(d10, d11));
        float s2b1 = hsum2(add2(d20, d21));

        s0b0 += __shfl_xor_sync(smask, s0b0, 1); s0b0 += __shfl_xor_sync(smask, s0b0, 2);
        s1b0 += __shfl_xor_sync(smask, s1b0, 1); s1b0 += __shfl_xor_sync(smask, s1b0, 2);
        s2b0 += __shfl_xor_sync(smask, s2b0, 1); s2b0 += __shfl_xor_sync(smask, s2b0, 2);
        s0b1 += __shfl_xor_sync(smask, s0b1, 1); s0b1 += __shfl_xor_sync(smask, s0b1, 2);
        s1b1 += __shfl_xor_sync(smask, s1b1, 1); s1b1 += __shfl_xor_sync(smask, s1b1, 2);
        s2b1 += __shfl_xor_sync(smask, s2b1, 1); s2b1 += __shfl_xor_sync(smask, s2b1, 2);

        if (fin) {
            float hr = (c == 0) ? s0b0 : s0b1;
            float hz = (c == 0) ? s1b0 : s1b1;
            float hn = (c == 0) ? s2b0 : s2b1;
            float r = sigf(gv0 + hr + bh0);
            float z = sigf(gv1 + hz + bh1);
            float n = tanh_acc(gv2 + r * (hn + bh2));
            float hnew = n + z * (hprev - n);
            hprev = hnew;
            hs += hnew;
            hm = fmaxf(hm, hnew);
            rs->h[1 - bp][c][h] = hnew;
        }
        gv0 = gn0; gv1 = gn1; gv2 = gn2;

        if ((t & 15) == 15 && tid == 0) wait_gi(t + 17);
        __syncthreads();
        bp ^= 1;
    }

    if (fin) {
        float inv = 1.0f / len0[b0 + c];
        rs->feat[c][h]     = hs * inv;
        rs->feat[c][H + h] = hm;
    }
    __syncthreads();

    if (tid < 2 * NCLS) {
        int bb = tid / NCLS, cc = tid % NCLS;
        const float* wr = W_out + cc * 2 * H;
        float acc = b_out[cc];
        #pragma unroll 4
        for (int j = 0; j < 2 * H; j++) acc += rs->feat[bb][j] * wr[j];
        out[(b0 + bb) * NCLS + cc] = acc;
    }
    __syncthreads();

    if (tid == 0) {
        int d = atomicAdd(&g_done, 1);
        if (d == NCTAS - 1) {
            #pragma unroll
            for (int i = 0; i < NPROD; i++) g_flagi[i] = 0;
            __threadfence();
            g_done = 0;
        }
    }
}

extern "C" void kernel_launch(void* const* d_in, const int* in_sizes, int n_in,
                              void* d_out, int out_size)
{
    const float* mfcc0 = (const float*)d_in[0];
    const float* mfcc1 = (const float*)d_in[1];
    const float* mfcc2 = (const float*)d_in[2];
    const float* len0  = (const float*)d_in[3];
    const float* W_ih  = (const float*)d_in[4];
    const float* W_hh  = (const float*)d_in[5];
    const float* b_ih  = (const float*)d_in[6];
    const float* b_hh  = (const float*)d_in[7];
    const float* W_out = (const float*)d_in[8];
    const float* b_out = (const float*)d_in[9];
    float* out = (float*)d_out;

    gru_fused_kernel<<<NCTAS, 400>>>(mfcc0, mfcc1, mfcc2, len0,
                                     W_ih, W_hh, b_ih, b_hh,
                                     W_out, b_out, out);
}